// round 14
// baseline (speedup 1.0000x reference)
#include <cuda_runtime.h>
#include <cuda_fp16.h>
#include <cstdint>

// ---------------- constants ----------------
#define B_SZ   16
#define LINES  128
#define WPL    32
#define NLINE  (B_SZ*LINES)          // 2048
#define EMB_D  300
#define AD     400
#define HEADS  8
#define DPH    50
#define NCAT   1200                  // q|k|v concatenated
#define VOCAB  30000
#define INV_SQRT50 0.14142135623730951f
#define NEGPEN 1e7f

#define KPAD_W  320                  // word-proj K pad (300 -> 320)
#define KPAD_L  416                  // line-proj K pad (400 -> 416)

// ---------------- scratch (device globals; no allocation allowed) ----------------
// vproj layout: [vocab][head][q(50)|k(50)|v(50)] -> contiguous 300B per (tok,head)
__device__ __align__(16) __half g_vprojh[(long)VOCAB * NCAT];
__device__ float g_lineE[NLINE * AD];          // [2048][400]
__device__ float g_lqkv[NLINE * NCAT];         // [2048][1200]
__device__ float g_docE[B_SZ * AD];            // [16][400]
__device__ __align__(16) __half g_WBhi[NCAT * KPAD_W];  // word weights [1200][320]
__device__ __align__(16) __half g_WBlo[NCAT * KPAD_W];
__device__ __align__(16) __half g_Ahi[(long)VOCAB * KPAD_W];  // emb [30000][320]
__device__ __align__(16) __half g_Alo[(long)VOCAB * KPAD_W];
__device__ __align__(16) __half g_LBhi[NCAT * KPAD_L];  // line weights [1200][416]
__device__ __align__(16) __half g_LBlo[NCAT * KPAD_L];
__device__ __align__(16) __half g_A2hi[NLINE * KPAD_L]; // lineE [2048][416]
__device__ __align__(16) __half g_A2lo[NLINE * KPAD_L];

// ---------------- PTX helpers (baseline ISA only) ----------------
__device__ __forceinline__ void cp16(void* dst, const void* src) {
    uint32_t d = (uint32_t)__cvta_generic_to_shared(dst);
    asm volatile("cp.async.ca.shared.global [%0], [%1], 16;" :: "r"(d), "l"(src));
}
__device__ __forceinline__ void cp_commit() {
    asm volatile("cp.async.commit_group;" ::: "memory");
}
template<int N>
__device__ __forceinline__ void cp_wait() {
    asm volatile("cp.async.wait_group %0;" :: "n"(N) : "memory");
}
__device__ __forceinline__ void mma16816(float* c, const uint32_t* a, const uint32_t* b) {
    asm volatile("mma.sync.aligned.m16n8k16.row.col.f32.f16.f16.f32 "
        "{%0,%1,%2,%3}, {%4,%5,%6,%7}, {%8,%9}, {%0,%1,%2,%3};"
        : "+f"(c[0]), "+f"(c[1]), "+f"(c[2]), "+f"(c[3])
        : "r"(a[0]), "r"(a[1]), "r"(a[2]), "r"(a[3]), "r"(b[0]), "r"(b[1]));
}
__device__ __forceinline__ void ldsm_x4(uint32_t* r, uint32_t addr) {
    asm volatile("ldmatrix.sync.aligned.m8n8.x4.shared.b16 {%0,%1,%2,%3}, [%4];"
        : "=r"(r[0]), "=r"(r[1]), "=r"(r[2]), "=r"(r[3]) : "r"(addr));
}
__device__ __forceinline__ void ldsm_x2(uint32_t* r, uint32_t addr) {
    asm volatile("ldmatrix.sync.aligned.m8n8.x2.shared.b16 {%0,%1}, [%2];"
        : "=r"(r[0]), "=r"(r[1]) : "r"(addr));
}

// =====================================================================
// Prep: split weight trio [K][400]x3 -> hi/lo [1200 n][kpad] fp16
// =====================================================================
__global__ __launch_bounds__(256)
void splitW_kernel(const float* __restrict__ W0, const float* __restrict__ W1,
                   const float* __restrict__ W2, int K, int kpad,
                   __half* __restrict__ outHi, __half* __restrict__ outLo)
{
    int idx = blockIdx.x * 256 + threadIdx.x;
    if (idx >= NCAT * (kpad / 2)) return;
    int n  = idx / (kpad / 2);
    int k0 = (idx % (kpad / 2)) * 2;
    const float* W = (n < AD) ? W0 : (n < 2 * AD ? W1 : W2);
    int lc = (n < AD) ? n : (n < 2 * AD ? n - AD : n - 2 * AD);
    float x0 = (k0     < K) ? W[(long)k0 * AD + lc]       : 0.f;
    float x1 = (k0 + 1 < K) ? W[(long)(k0 + 1) * AD + lc] : 0.f;
    __half h0 = __float2half(x0), h1 = __float2half(x1);
    __half l0 = __float2half(x0 - __half2float(h0));
    __half l1 = __float2half(x1 - __half2float(h1));
    *reinterpret_cast<__half2*>(outHi + (long)n * kpad + k0) = __halves2half2(h0, h1);
    *reinterpret_cast<__half2*>(outLo + (long)n * kpad + k0) = __halves2half2(l0, l1);
}

// =====================================================================
// Prep: split row-major A [M][K] fp32 -> hi/lo [M][kpad] fp16
// =====================================================================
__global__ __launch_bounds__(256)
void splitA_kernel(const float* __restrict__ A, int M, int K, int kpad,
                   __half* __restrict__ outHi, __half* __restrict__ outLo)
{
    long idx = (long)blockIdx.x * 256 + threadIdx.x;
    if (idx >= (long)M * (kpad / 2)) return;
    int m  = (int)(idx / (kpad / 2));
    int k0 = (int)(idx % (kpad / 2)) * 2;
    float x0 = 0.f, x1 = 0.f;
    if (k0 + 1 < K) {
        float2 v = *reinterpret_cast<const float2*>(A + (long)m * K + k0);
        x0 = v.x; x1 = v.y;
    } else if (k0 < K) {
        x0 = A[(long)m * K + k0];
    }
    __half h0 = __float2half(x0), h1 = __float2half(x1);
    __half l0 = __float2half(x0 - __half2float(h0));
    __half l1 = __float2half(x1 - __half2float(h1));
    *reinterpret_cast<__half2*>(outHi + (long)m * kpad + k0) = __halves2half2(h0, h1);
    *reinterpret_cast<__half2*>(outLo + (long)m * kpad + k0) = __halves2half2(l0, l1);
}

// =====================================================================
// Streaming HMMA GEMM + bias + ELU (fp16 hi/lo 3-term), ldmatrix fragments.
// OT=__half: word proj, writes head-major layout. OT=float: line proj.
// Prefetch src/dst addresses hoisted out of the chunk loop (ALU tax fix).
// =====================================================================
#define GKC    32
#define GPITCH 40                       // halves per chunk-row (80B, conflict-free)
#define ABUF   (128 * GPITCH)           // 5120 halves
#define BBUF   (80 * GPITCH)            // 3200 halves
#define GEMM_SMEM ((4 * ABUF + 4 * BBUF) * 2)   // 66560 B

template<typename OT>
__global__ __launch_bounds__(256, 2)
void gemm_elu_kernel(const __half* __restrict__ Ahi, const __half* __restrict__ Alo,
                     int M, int kpad, int nchunks,
                     const __half* __restrict__ Bhi, const __half* __restrict__ Blo,
                     const float* __restrict__ Bb0, const float* __restrict__ Bb1,
                     const float* __restrict__ Bb2,
                     OT* __restrict__ out)
{
    extern __shared__ __half sh[];
    __half* sA = sh;                    // [buf][split][128][GPITCH]
    __half* sB = sh + 4 * ABUF;         // [buf][split][80][GPITCH]

    const int tid  = threadIdx.x;
    const int wid  = tid >> 5;
    const int lane = tid & 31;
    const int g4 = lane >> 2;
    const int l4 = lane & 3;
    const int wm = wid >> 1;            // 0..3 (M slab of 32)
    const int wn = wid & 1;             // 0..1 (N slab of 40)
    const int bx = blockIdx.x;
    const int nt = blockIdx.y;          // 0..14

    const uint32_t sbase = (uint32_t)__cvta_generic_to_shared(sh);
    const uint32_t aBase = sbase
        + (uint32_t)(((wm * 32 + (lane & 15)) * GPITCH + (lane >> 4) * 8) * 2);
    const uint32_t bBase = sbase + (uint32_t)(8 * ABUF)
        + (uint32_t)(((wn * 40 + (lane & 7) + ((lane >> 4) & 1) * 8) * GPITCH
                     + ((lane >> 3) & 1) * 8) * 2);

    // ---- hoisted prefetch addresses (fixed src row/seg; only k advances) ----
    const __half* srcA[4];
    __half*       dstA[4];
    #pragma unroll
    for (int it = 0; it < 4; it++) {
        int idx = tid + it * 256;
        int split = idx >> 9;
        int rem = idx & 511;
        int r = rem >> 2;
        int seg = rem & 3;
        int row = bx * 128 + r;
        if (row >= M) row = M - 1;
        srcA[it] = (split ? Alo : Ahi) + (long)row * kpad + seg * 8;
        dstA[it] = sA + split * ABUF + r * GPITCH + seg * 8;
    }
    const __half* srcB[3];
    __half*       dstB[3];
    bool          vB[3];
    #pragma unroll
    for (int it = 0; it < 3; it++) {
        int idx = tid + it * 256;
        vB[it] = (idx < 640);
        int split = (idx >= 320) ? 1 : 0;
        int rem = idx - split * 320;
        if (rem > 319) rem = 319;
        int r = rem >> 2;
        int seg = rem & 3;
        srcB[it] = (split ? Blo : Bhi) + (long)(nt * 80 + r) * kpad + seg * 8;
        dstB[it] = sB + split * BBUF + r * GPITCH + seg * 8;
    }

    auto prefetch = [&](int c) {
        const int bufA = (c & 1) * 2 * ABUF;
        const int bufB = (c & 1) * 2 * BBUF;
        const int kb = c * GKC;
        #pragma unroll
        for (int it = 0; it < 4; it++) cp16(dstA[it] + bufA, srcA[it] + kb);
        #pragma unroll
        for (int it = 0; it < 3; it++)
            if (vB[it]) cp16(dstB[it] + bufB, srcB[it] + kb);
    };

    float acc[2][5][4];
    #pragma unroll
    for (int mi = 0; mi < 2; mi++)
        #pragma unroll
        for (int ni = 0; ni < 5; ni++)
            #pragma unroll
            for (int r = 0; r < 4; r++) acc[mi][ni][r] = 0.f;

    prefetch(0);
    cp_commit();

    for (int c = 0; c < nchunks; c++) {
        if (c + 1 < nchunks) { prefetch(c + 1); cp_commit(); cp_wait<1>(); }
        else                 { cp_wait<0>(); }
        __syncthreads();

        const int buf = c & 1;
        const uint32_t aOffH = (uint32_t)(buf * 4 * ABUF);        // bytes
        const uint32_t aOffL = aOffH + (uint32_t)(2 * ABUF);
        const uint32_t bOffH = (uint32_t)(buf * 4 * BBUF);
        const uint32_t bOffL = bOffH + (uint32_t)(2 * BBUF);

        #pragma unroll
        for (int ks = 0; ks < 2; ks++) {
            const uint32_t ksOff = (uint32_t)(ks * 32);           // 16 halves
            uint32_t ah[2][4], al[2][4], bh[5][2], bl[5][2];
            ldsm_x4(ah[0], aBase + aOffH + ksOff);
            ldsm_x4(ah[1], aBase + aOffH + 16 * GPITCH * 2 + ksOff);
            ldsm_x4(al[0], aBase + aOffL + ksOff);
            ldsm_x4(al[1], aBase + aOffL + 16 * GPITCH * 2 + ksOff);
            ldsm_x4(&bh[0][0], bBase + bOffH + ksOff);
            ldsm_x4(&bh[2][0], bBase + bOffH + 16 * GPITCH * 2 + ksOff);
            ldsm_x2(&bh[4][0], bBase + bOffH + 32 * GPITCH * 2 + ksOff);
            ldsm_x4(&bl[0][0], bBase + bOffL + ksOff);
            ldsm_x4(&bl[2][0], bBase + bOffL + 16 * GPITCH * 2 + ksOff);
            ldsm_x2(&bl[4][0], bBase + bOffL + 32 * GPITCH * 2 + ksOff);

            #pragma unroll
            for (int mi = 0; mi < 2; mi++)
                #pragma unroll
                for (int ni = 0; ni < 5; ni++) {
                    mma16816(acc[mi][ni], ah[mi], bh[ni]);
                    mma16816(acc[mi][ni], ah[mi], bl[ni]);
                    mma16816(acc[mi][ni], al[mi], bh[ni]);
                }
        }
        __syncthreads();
    }

    // ---- epilogue: bias + ELU + guarded store ----
    const int sel = nt / 5;
    const float* Bb = (sel == 0) ? Bb0 : (sel == 1 ? Bb1 : Bb2);
    const int cb = nt * 80 - sel * AD;
    #pragma unroll
    for (int mi = 0; mi < 2; mi++) {
        #pragma unroll
        for (int r01 = 0; r01 < 2; r01++) {
            const int row = bx * 128 + wm * 32 + mi * 16 + g4 + r01 * 8;
            if (row < M) {
                #pragma unroll
                for (int ni = 0; ni < 5; ni++) {
                    int lc = cb + wn * 40 + ni * 8 + l4 * 2;   // 0..399 within matrix
                    float x0 = acc[mi][ni][r01 * 2 + 0] + Bb[lc];
                    float x1 = acc[mi][ni][r01 * 2 + 1] + Bb[lc + 1];
                    float o0 = (x0 > 0.f) ? x0 : expm1f(x0);
                    float o1 = (x1 > 0.f) ? x1 : expm1f(x1);
                    if (sizeof(OT) == 2) {
                        // head-major remap: [h][sel][d]
                        int h = lc / DPH, d = lc % DPH;
                        int col = h * (3 * DPH) + sel * DPH + d;
                        *reinterpret_cast<__half2*>((__half*)out + (long)row * NCAT + col)
                            = __floats2half2_rn(o0, o1);
                    } else {
                        int col = nt * 80 + wn * 40 + ni * 8 + l4 * 2;
                        *reinterpret_cast<float2*>((float*)out + (long)row * NCAT + col)
                            = make_float2(o0, o1);
                    }
                }
            }
        }
    }
}

// =====================================================================
// Word-level attention + target attention.  One block per (line, head).
// One contiguous 300B fp16 read per (token,head) from the head-major table.
// =====================================================================
__global__ __launch_bounds__(128)
void watt_kernel(const int* __restrict__ docs, const float* __restrict__ w_tgt,
                 float* __restrict__ lineE)
{
    const int line = blockIdx.x;
    const int h    = blockIdx.y;
    const int tid  = threadIdx.x;

    __shared__ float q[WPL * DPH], k[WPL * DPH], v[WPL * DPH];
    __shared__ float ws[WPL * 33];
    __shared__ float watt[WPL * DPH];
    __shared__ float tw[WPL];
    __shared__ int   msk[WPL];
    __shared__ int   stok[WPL];

    if (tid < WPL) {
        int t = docs[line * WPL + tid];
        stok[tid] = t;
        msk[tid] = (t != 0);
    }
    __syncthreads();
    // 75 half2 per (token,head), contiguous: q[0..24] k[25..49] v[50..74]
    for (int i = tid; i < WPL * 75; i += 128) {
        int w = i / 75, e = i % 75;
        long base = (long)stok[w] * NCAT + h * (3 * DPH) + e * 2;
        float2 f = __half22float2(*reinterpret_cast<const __half2*>(g_vprojh + base));
        int slab = e / 25;
        int d = (e % 25) * 2;
        float* dst = (slab == 0) ? q : (slab == 1 ? k : v);
        dst[w * DPH + d]     = f.x;
        dst[w * DPH + d + 1] = f.y;
    }
    __syncthreads();

    {
        int i0 = (tid >> 3) * 2;
        int j0 = (tid & 7) * 4;
        float s0[4] = {0.f, 0.f, 0.f, 0.f};
        float s1[4] = {0.f, 0.f, 0.f, 0.f};
        for (int d = 0; d < DPH; d++) {
            float qa = q[i0 * DPH + d];
            float qb = q[(i0 + 1) * DPH + d];
            #pragma unroll
            for (int jj = 0; jj < 4; jj++) {
                float kv = k[(j0 + jj) * DPH + d];
                s0[jj] = fmaf(qa, kv, s0[jj]);
                s1[jj] = fmaf(qb, kv, s1[jj]);
            }
        }
        #pragma unroll
        for (int jj = 0; jj < 4; jj++) {
            float m = msk[j0 + jj] ? 0.f : NEGPEN;
            ws[i0 * 33 + j0 + jj]       = s0[jj] * INV_SQRT50 - m;
            ws[(i0 + 1) * 33 + j0 + jj] = s1[jj] * INV_SQRT50 - m;
        }
    }
    __syncthreads();

    {
        int wi = tid >> 5, ln = tid & 31;
        for (int r = wi; r < WPL; r += 4) {
            float x = ws[r * 33 + ln];
            float mx = x;
            #pragma unroll
            for (int o = 16; o; o >>= 1) mx = fmaxf(mx, __shfl_xor_sync(~0u, mx, o));
            float e = __expf(x - mx);
            float sm = e;
            #pragma unroll
            for (int o = 16; o; o >>= 1) sm += __shfl_xor_sync(~0u, sm, o);
            float wv = e / sm;
            if (!msk[r]) wv = 0.f;
            ws[r * 33 + ln] = wv;
        }
    }
    __syncthreads();

    for (int u = tid; u < (WPL / 2) * DPH; u += 128) {
        int ip = u / DPH, d = u % DPH;
        int i0 = ip * 2;
        float a0 = 0.f, a1 = 0.f;
        for (int j = 0; j < WPL; j++) {
            float vv = v[j * DPH + d];
            a0 = fmaf(ws[i0 * 33 + j], vv, a0);
            a1 = fmaf(ws[(i0 + 1) * 33 + j], vv, a1);
        }
        watt[i0 * DPH + d] = a0;
        watt[(i0 + 1) * DPH + d] = a1;
    }
    __syncthreads();

    if (tid < WPL) {
        int j = tid;
        float s = 0.f;
        for (int d = 0; d < DPH; d++)
            s = fmaf(w_tgt[h * DPH + d], k[j * DPH + d], s);
        s *= INV_SQRT50;
        if (!msk[j]) s -= NEGPEN;
        float mx = s;
        #pragma unroll
        for (int o = 16; o; o >>= 1) mx = fmaxf(mx, __shfl_xor_sync(~0u, mx, o));
        float e = __expf(s - mx);
        float sm = e;
        #pragma unroll
        for (int o = 16; o; o >>= 1) sm += __shfl_xor_sync(~0u, sm, o);
        tw[j] = e / sm;
    }
    __syncthreads();

    if (tid < DPH) {
        int d = tid;
        float a = 0.f;
        for (int j = 0; j < WPL; j++) a = fmaf(tw[j], watt[j * DPH + d], a);
        lineE[(long)line * AD + h * DPH + d] = a;
    }
}

// =====================================================================
// Line-level attention + doc target attention.  One block per (doc, head).
// =====================================================================
#define LA_Q  0
#define LA_K  (LINES * DPH)
#define LA_V  (2 * LINES * DPH)
#define LA_A  (3 * LINES * DPH)
#define LA_S  (4 * LINES * DPH)
#define LA_FLOATS (LA_S + LINES * 129)
#define LA_SMEM_BYTES (LA_FLOATS * 4)
#define LA_THREADS 512

__global__ __launch_bounds__(LA_THREADS)
void latt_kernel(const int* __restrict__ docs, const float* __restrict__ l_tgt,
                 float* __restrict__ docE)
{
    extern __shared__ float sm[];
    __shared__ int   mskL[LINES];
    __shared__ float ts[LINES];

    const int doc = blockIdx.x;
    const int h   = blockIdx.y;
    const int tid = threadIdx.x;

    if (tid < LINES) {
        int any = 0;
        const int* p = docs + (long)(doc * LINES + tid) * WPL;
        for (int w = 0; w < WPL; w++) any |= p[w];
        mskL[tid] = (any != 0);
    }
    for (int i = tid; i < LINES * DPH; i += LA_THREADS) {
        int l = i / DPH, d = i % DPH;
        long base = (long)(doc * LINES + l) * NCAT + h * DPH + d;
        sm[LA_Q + i] = g_lqkv[base];
        sm[LA_K + i] = g_lqkv[base + AD];
        sm[LA_V + i] = g_lqkv[base + 2 * AD];
    }
    __syncthreads();

    for (int u = tid; u < (LINES / 2) * (LINES / 4); u += LA_THREADS) {
        int ip = u >> 5;
        int jq = u & 31;
        int i0 = ip * 2, j0 = jq * 4;
        float s0[4] = {0.f, 0.f, 0.f, 0.f};
        float s1[4] = {0.f, 0.f, 0.f, 0.f};
        for (int d = 0; d < DPH; d++) {
            float qa = sm[LA_Q + i0 * DPH + d];
            float qb = sm[LA_Q + (i0 + 1) * DPH + d];
            #pragma unroll
            for (int jj = 0; jj < 4; jj++) {
                float kv = sm[LA_K + (j0 + jj) * DPH + d];
                s0[jj] = fmaf(qa, kv, s0[jj]);
                s1[jj] = fmaf(qb, kv, s1[jj]);
            }
        }
        #pragma unroll
        for (int jj = 0; jj < 4; jj++) {
            float m = mskL[j0 + jj] ? 0.f : NEGPEN;
            sm[LA_S + i0 * 129 + j0 + jj]       = s0[jj] * INV_SQRT50 - m;
            sm[LA_S + (i0 + 1) * 129 + j0 + jj] = s1[jj] * INV_SQRT50 - m;
        }
    }
    __syncthreads();

    {
        int wi = tid >> 5, ln = tid & 31;
        for (int r = wi; r < LINES; r += (LA_THREADS / 32)) {
            float x0 = sm[LA_S + r * 129 + ln];
            float x1 = sm[LA_S + r * 129 + ln + 32];
            float x2 = sm[LA_S + r * 129 + ln + 64];
            float x3 = sm[LA_S + r * 129 + ln + 96];
            float mx = fmaxf(fmaxf(x0, x1), fmaxf(x2, x3));
            #pragma unroll
            for (int o = 16; o; o >>= 1) mx = fmaxf(mx, __shfl_xor_sync(~0u, mx, o));
            float e0 = __expf(x0 - mx), e1 = __expf(x1 - mx);
            float e2 = __expf(x2 - mx), e3 = __expf(x3 - mx);
            float smv = e0 + e1 + e2 + e3;
            #pragma unroll
            for (int o = 16; o; o >>= 1) smv += __shfl_xor_sync(~0u, smv, o);
            float inv = (mskL[r] ? 1.f : 0.f) / smv;
            sm[LA_S + r * 129 + ln]      = e0 * inv;
            sm[LA_S + r * 129 + ln + 32] = e1 * inv;
            sm[LA_S + r * 129 + ln + 64] = e2 * inv;
            sm[LA_S + r * 129 + ln + 96] = e3 * inv;
        }
    }
    __syncthreads();

    for (int u = tid; u < (LINES / 2) * DPH; u += LA_THREADS) {
        int ip = u / DPH, d = u % DPH;
        int i0 = ip * 2;
        float a0 = 0.f, a1 = 0.f;
        for (int j = 0; j < LINES; j++) {
            float vv = sm[LA_V + j * DPH + d];
            a0 = fmaf(sm[LA_S + i0 * 129 + j], vv, a0);
            a1 = fmaf(sm[LA_S + (i0 + 1) * 129 + j], vv, a1);
        }
        sm[LA_A + i0 * DPH + d] = a0;
        sm[LA_A + (i0 + 1) * DPH + d] = a1;
    }
    __syncthreads();

    if (tid < LINES) {
        int j = tid;
        float s = 0.f;
        for (int d = 0; d < DPH; d++)
            s = fmaf(l_tgt[h * DPH + d], sm[LA_K + j * DPH + d], s);
        s *= INV_SQRT50;
        if (!mskL[j]) s -= NEGPEN;
        ts[j] = s;
    }
    __syncthreads();
    if (tid < 32) {
        int ln = tid;
        float x0 = ts[ln], x1 = ts[ln + 32], x2 = ts[ln + 64], x3 = ts[ln + 96];
        float mx = fmaxf(fmaxf(x0, x1), fmaxf(x2, x3));
        #pragma unroll
        for (int o = 16; o; o >>= 1) mx = fmaxf(mx, __shfl_xor_sync(~0u, mx, o));
        float e0 = __expf(x0 - mx), e1 = __expf(x1 - mx);
        float e2 = __expf(x2 - mx), e3 = __expf(x3 - mx);
        float smv = e0 + e1 + e2 + e3;
        #pragma unroll
        for (int o = 16; o; o >>= 1) smv += __shfl_xor_sync(~0u, smv, o);
        float inv = 1.f / smv;
        ts[ln] = e0 * inv; ts[ln + 32] = e1 * inv;
        ts[ln + 64] = e2 * inv; ts[ln + 96] = e3 * inv;
    }
    __syncthreads();
    if (tid < DPH) {
        int d = tid;
        float a = 0.f;
        for (int j = 0; j < LINES; j++) a = fmaf(ts[j], sm[LA_A + j * DPH + d], a);
        docE[(long)doc * AD + h * DPH + d] = a;
    }
}

// =====================================================================
// Final FC
// =====================================================================
__global__ __launch_bounds__(608)
void fc_kernel(const float* __restrict__ fc1w, const float* __restrict__ fc1b,
               const float* __restrict__ fc2w, const float* __restrict__ fc2b,
               float* __restrict__ out)
{
    const int b = blockIdx.x;
    const int tid = threadIdx.x;
    __shared__ float de[AD];
    for (int i = tid; i < AD; i += 608) de[i] = g_docE[b * AD + i];
    __syncthreads();
    if (tid < 582) {
        float a;
        if (tid < 70) {
            a = fc1b[tid];
            for (int kk = 0; kk < AD; kk++) a = fmaf(de[kk], fc1w[kk * 70 + tid], a);
        } else {
            int c = tid - 70;
            a = fc2b[c];
            for (int kk = 0; kk < AD; kk++) a = fmaf(de[kk], fc2w[kk * 512 + c], a);
        }
        out[b * 582 + tid] = a;
    }
}

// =====================================================================
extern "C" void kernel_launch(void* const* d_in, const int* in_sizes, int n_in,
                              void* d_out, int out_size)
{
    const int*   docs  = (const int*)  d_in[0];
    const float* emb   = (const float*)d_in[1];
    const float* wq_w  = (const float*)d_in[2];
    const float* wq_b  = (const float*)d_in[3];
    const float* wk_w  = (const float*)d_in[4];
    const float* wk_b  = (const float*)d_in[5];
    const float* wv_w  = (const float*)d_in[6];
    const float* wv_b  = (const float*)d_in[7];
    const float* w_tgt = (const float*)d_in[8];
    const float* lq_w  = (const float*)d_in[9];
    const float* lq_b  = (const float*)d_in[10];
    const float* lk_w  = (const float*)d_in[11];
    const float* lk_b  = (const float*)d_in[12];
    const float* lv_w  = (const float*)d_in[13];
    const float* lv_b  = (const float*)d_in[14];
    const float* l_tgt = (const float*)d_in[15];
    const float* fc1_w = (const float*)d_in[16];
    const float* fc1_b = (const float*)d_in[17];
    const float* fc2_w = (const float*)d_in[18];
    const float* fc2_b = (const float*)d_in[19];
    float* out = (float*)d_out;

    float *lineE, *lqkv, *docE;
    __half *vprojh, *wbhi, *wblo, *ahi, *alo, *lbhi, *lblo, *a2hi, *a2lo;
    cudaGetSymbolAddress((void**)&vprojh, g_vprojh);
    cudaGetSymbolAddress((void**)&lineE, g_lineE);
    cudaGetSymbolAddress((void**)&lqkv,  g_lqkv);
    cudaGetSymbolAddress((void**)&docE,  g_docE);
    cudaGetSymbolAddress((void**)&wbhi,  g_WBhi);
    cudaGetSymbolAddress((void**)&wblo,  g_WBlo);
    cudaGetSymbolAddress((void**)&ahi,   g_Ahi);
    cudaGetSymbolAddress((void**)&alo,   g_Alo);
    cudaGetSymbolAddress((void**)&lbhi,  g_LBhi);
    cudaGetSymbolAddress((void**)&lblo,  g_LBlo);
    cudaGetSymbolAddress((void**)&a2hi,  g_A2hi);
    cudaGetSymbolAddress((void**)&a2lo,  g_A2lo);

    // 0) weight + emb splits
    splitW_kernel<<<(NCAT * (KPAD_W / 2) + 255) / 256, 256>>>(
        wq_w, wk_w, wv_w, EMB_D, KPAD_W, wbhi, wblo);
    splitW_kernel<<<(NCAT * (KPAD_L / 2) + 255) / 256, 256>>>(
        lq_w, lk_w, lv_w, AD, KPAD_L, lbhi, lblo);
    splitA_kernel<<<(int)(((long)VOCAB * (KPAD_W / 2) + 255) / 256), 256>>>(
        emb, VOCAB, EMB_D, KPAD_W, ahi, alo);

    // 1) vocab-wide word projection -> fp16 head-major table
    cudaFuncSetAttribute(gemm_elu_kernel<__half>,
                         cudaFuncAttributeMaxDynamicSharedMemorySize, GEMM_SMEM);
    cudaFuncSetAttribute(gemm_elu_kernel<float>,
                         cudaFuncAttributeMaxDynamicSharedMemorySize, GEMM_SMEM);
    gemm_elu_kernel<__half><<<dim3((VOCAB + 127) / 128, 15), 256, GEMM_SMEM>>>(
        ahi, alo, VOCAB, KPAD_W, KPAD_W / GKC,
        wbhi, wblo, wq_b, wk_b, wv_b, vprojh);

    // 2) word attention + target attention -> line_e [2048,400]
    watt_kernel<<<dim3(NLINE, HEADS), 128>>>(docs, w_tgt, lineE);

    // 3) line projection (fp32 output)
    splitA_kernel<<<(NLINE * (KPAD_L / 2) + 255) / 256, 256>>>(
        lineE, NLINE, AD, KPAD_L, a2hi, a2lo);
    gemm_elu_kernel<float><<<dim3(NLINE / 128, 15), 256, GEMM_SMEM>>>(
        a2hi, a2lo, NLINE, KPAD_L, KPAD_L / GKC,
        lbhi, lblo, lq_b, lk_b, lv_b, lqkv);

    // 4) line attention + doc target attention -> doc_e [16,400]
    cudaFuncSetAttribute(latt_kernel, cudaFuncAttributeMaxDynamicSharedMemorySize,
                         LA_SMEM_BYTES);
    latt_kernel<<<dim3(B_SZ, HEADS), LA_THREADS, LA_SMEM_BYTES>>>(docs, l_tgt, docE);

    // 5) final FC -> [16,582]
    fc_kernel<<<B_SZ, 608>>>(fc1_w, fc1_b, fc2_w, fc2_b, out);
}

// round 15
// speedup vs baseline: 1.1226x; 1.1226x over previous
#include <cuda_runtime.h>
#include <cuda_fp16.h>
#include <cstdint>

// ---------------- constants ----------------
#define B_SZ   16
#define LINES  128
#define WPL    32
#define NLINE  (B_SZ*LINES)          // 2048
#define EMB_D  300
#define AD     400
#define HEADS  8
#define DPH    50
#define NCAT   1200                  // q|k|v concatenated
#define VOCAB  30000
#define INV_SQRT50 0.14142135623730951f
#define NEGPEN 1e7f

#define KPAD_W  320                  // word-proj K pad (300 -> 320)
#define KPAD_L  416                  // line-proj K pad (400 -> 416)

// ---------------- scratch (device globals; no allocation allowed) ----------------
__device__ __align__(16) __half g_vprojh[(long)VOCAB * NCAT]; // [30000][1200] fp16
__device__ float g_lineE[NLINE * AD];          // [2048][400]
__device__ float g_lqkv[NLINE * NCAT];         // [2048][1200]
__device__ float g_docE[B_SZ * AD];            // [16][400]
__device__ __align__(16) __half g_WBhi[NCAT * KPAD_W];  // word weights [1200][320]
__device__ __align__(16) __half g_WBlo[NCAT * KPAD_W];
__device__ __align__(16) __half g_Ahi[(long)VOCAB * KPAD_W];  // emb [30000][320]
__device__ __align__(16) __half g_Alo[(long)VOCAB * KPAD_W];
__device__ __align__(16) __half g_LBhi[NCAT * KPAD_L];  // line weights [1200][416]
__device__ __align__(16) __half g_LBlo[NCAT * KPAD_L];
__device__ __align__(16) __half g_A2hi[NLINE * KPAD_L]; // lineE [2048][416]
__device__ __align__(16) __half g_A2lo[NLINE * KPAD_L];

// ---------------- PTX helpers (baseline ISA only) ----------------
__device__ __forceinline__ void cp16(void* dst, const void* src) {
    uint32_t d = (uint32_t)__cvta_generic_to_shared(dst);
    asm volatile("cp.async.ca.shared.global [%0], [%1], 16;" :: "r"(d), "l"(src));
}
__device__ __forceinline__ void cp_commit() {
    asm volatile("cp.async.commit_group;" ::: "memory");
}
template<int N>
__device__ __forceinline__ void cp_wait() {
    asm volatile("cp.async.wait_group %0;" :: "n"(N) : "memory");
}
__device__ __forceinline__ void mma16816(float* c, const uint32_t* a, const uint32_t* b) {
    asm volatile("mma.sync.aligned.m16n8k16.row.col.f32.f16.f16.f32 "
        "{%0,%1,%2,%3}, {%4,%5,%6,%7}, {%8,%9}, {%0,%1,%2,%3};"
        : "+f"(c[0]), "+f"(c[1]), "+f"(c[2]), "+f"(c[3])
        : "r"(a[0]), "r"(a[1]), "r"(a[2]), "r"(a[3]), "r"(b[0]), "r"(b[1]));
}
__device__ __forceinline__ void ldsm_x4(uint32_t* r, uint32_t addr) {
    asm volatile("ldmatrix.sync.aligned.m8n8.x4.shared.b16 {%0,%1,%2,%3}, [%4];"
        : "=r"(r[0]), "=r"(r[1]), "=r"(r[2]), "=r"(r[3]) : "r"(addr));
}
__device__ __forceinline__ void ldsm_x2(uint32_t* r, uint32_t addr) {
    asm volatile("ldmatrix.sync.aligned.m8n8.x2.shared.b16 {%0,%1}, [%2];"
        : "=r"(r[0]), "=r"(r[1]) : "r"(addr));
}

// =====================================================================
// Prep: split weight trio [K][400]x3 -> hi/lo [1200 n][kpad] fp16
// =====================================================================
__global__ __launch_bounds__(256)
void splitW_kernel(const float* __restrict__ W0, const float* __restrict__ W1,
                   const float* __restrict__ W2, int K, int kpad,
                   __half* __restrict__ outHi, __half* __restrict__ outLo)
{
    int idx = blockIdx.x * 256 + threadIdx.x;
    if (idx >= NCAT * (kpad / 2)) return;
    int n  = idx / (kpad / 2);
    int k0 = (idx % (kpad / 2)) * 2;
    const float* W = (n < AD) ? W0 : (n < 2 * AD ? W1 : W2);
    int lc = (n < AD) ? n : (n < 2 * AD ? n - AD : n - 2 * AD);
    float x0 = (k0     < K) ? W[(long)k0 * AD + lc]       : 0.f;
    float x1 = (k0 + 1 < K) ? W[(long)(k0 + 1) * AD + lc] : 0.f;
    __half h0 = __float2half(x0), h1 = __float2half(x1);
    __half l0 = __float2half(x0 - __half2float(h0));
    __half l1 = __float2half(x1 - __half2float(h1));
    *reinterpret_cast<__half2*>(outHi + (long)n * kpad + k0) = __halves2half2(h0, h1);
    *reinterpret_cast<__half2*>(outLo + (long)n * kpad + k0) = __halves2half2(l0, l1);
}

// =====================================================================
// Prep: split row-major A [M][K] fp32 -> hi/lo [M][kpad] fp16
// =====================================================================
__global__ __launch_bounds__(256)
void splitA_kernel(const float* __restrict__ A, int M, int K, int kpad,
                   __half* __restrict__ outHi, __half* __restrict__ outLo)
{
    long idx = (long)blockIdx.x * 256 + threadIdx.x;
    if (idx >= (long)M * (kpad / 2)) return;
    int m  = (int)(idx / (kpad / 2));
    int k0 = (int)(idx % (kpad / 2)) * 2;
    float x0 = 0.f, x1 = 0.f;
    if (k0 + 1 < K) {
        float2 v = *reinterpret_cast<const float2*>(A + (long)m * K + k0);
        x0 = v.x; x1 = v.y;
    } else if (k0 < K) {
        x0 = A[(long)m * K + k0];
    }
    __half h0 = __float2half(x0), h1 = __float2half(x1);
    __half l0 = __float2half(x0 - __half2float(h0));
    __half l1 = __float2half(x1 - __half2float(h1));
    *reinterpret_cast<__half2*>(outHi + (long)m * kpad + k0) = __halves2half2(h0, h1);
    *reinterpret_cast<__half2*>(outLo + (long)m * kpad + k0) = __halves2half2(l0, l1);
}

// =====================================================================
// Streaming HMMA GEMM + bias + ELU, ldmatrix fragments.
// ALO=true : 3-term hi/lo (A_hi*B_hi + A_hi*B_lo + A_lo*B_hi)
// ALO=false: 2-term (A_hi*B_hi + A_hi*B_lo) — used for the word proj whose
//            output is fp16 anyway (A-residual below output quantization).
// Tile M128 x N80, KC=32 double-buffered cp.async. 256 thr (8 warps: 4M x 2N).
// =====================================================================
#define GKC    32
#define GPITCH 40                       // halves per chunk-row (80B, conflict-free)
#define ABUF   (128 * GPITCH)           // 5120 halves
#define BBUF   (80 * GPITCH)            // 3200 halves
#define GEMM_SMEM ((4 * ABUF + 4 * BBUF) * 2)   // 66560 B

template<typename OT, bool ALO>
__global__ __launch_bounds__(256)
void gemm_elu_kernel(const __half* __restrict__ Ahi, const __half* __restrict__ Alo,
                     int M, int kpad, int nchunks,
                     const __half* __restrict__ Bhi, const __half* __restrict__ Blo,
                     const float* __restrict__ Bb0, const float* __restrict__ Bb1,
                     const float* __restrict__ Bb2,
                     OT* __restrict__ out)
{
    extern __shared__ __half sh[];
    __half* sA = sh;                    // [buf][split][128][GPITCH]
    __half* sB = sh + 4 * ABUF;         // [buf][split][80][GPITCH]

    const int tid  = threadIdx.x;
    const int wid  = tid >> 5;
    const int lane = tid & 31;
    const int g4 = lane >> 2;
    const int l4 = lane & 3;
    const int wm = wid >> 1;            // 0..3 (M slab of 32)
    const int wn = wid & 1;             // 0..1 (N slab of 40)
    const int bx = blockIdx.x;
    const int nt = blockIdx.y;          // 0..14

    const uint32_t sbase = (uint32_t)__cvta_generic_to_shared(sh);
    const uint32_t aBase = sbase
        + (uint32_t)(((wm * 32 + (lane & 15)) * GPITCH + (lane >> 4) * 8) * 2);
    const uint32_t bBase = sbase + (uint32_t)(8 * ABUF)
        + (uint32_t)(((wn * 40 + (lane & 7) + ((lane >> 4) & 1) * 8) * GPITCH
                     + ((lane >> 3) & 1) * 8) * 2);

    auto prefetch = [&](int c) {
        const int buf = c & 1;
        const long kbase = (long)c * GKC;
        #pragma unroll
        for (int it = 0; it < 4; it++) {
            int idx = tid + it * 256;
            int split = idx >> 9;
            if (!ALO && split == 1) continue;    // A_lo unused in 2-term mode
            int rem = idx & 511;
            int r = rem >> 2;
            int seg = rem & 3;
            int row = bx * 128 + r;
            if (row >= M) row = M - 1;
            const __half* src = (split ? Alo : Ahi) + (long)row * kpad + kbase + seg * 8;
            __half* dst = sA + (buf * 2 + split) * ABUF + r * GPITCH + seg * 8;
            cp16(dst, src);
        }
        #pragma unroll
        for (int it = 0; it < 3; it++) {
            int idx = tid + it * 256;
            if (idx < 640) {
                int split = (idx >= 320) ? 1 : 0;
                int rem = idx - split * 320;
                int r = rem >> 2;
                int seg = rem & 3;
                const __half* src = (split ? Blo : Bhi)
                                  + (long)(nt * 80 + r) * kpad + kbase + seg * 8;
                __half* dst = sB + (buf * 2 + split) * BBUF + r * GPITCH + seg * 8;
                cp16(dst, src);
            }
        }
    };

    float acc[2][5][4];
    #pragma unroll
    for (int mi = 0; mi < 2; mi++)
        #pragma unroll
        for (int ni = 0; ni < 5; ni++)
            #pragma unroll
            for (int r = 0; r < 4; r++) acc[mi][ni][r] = 0.f;

    prefetch(0);
    cp_commit();

    for (int c = 0; c < nchunks; c++) {
        if (c + 1 < nchunks) { prefetch(c + 1); cp_commit(); cp_wait<1>(); }
        else                 { cp_wait<0>(); }
        __syncthreads();

        const int buf = c & 1;
        const uint32_t aOffH = (uint32_t)(buf * 4 * ABUF);        // bytes
        const uint32_t aOffL = aOffH + (uint32_t)(2 * ABUF);
        const uint32_t bOffH = (uint32_t)(buf * 4 * BBUF);
        const uint32_t bOffL = bOffH + (uint32_t)(2 * BBUF);

        #pragma unroll
        for (int ks = 0; ks < 2; ks++) {
            const uint32_t ksOff = (uint32_t)(ks * 32);           // 16 halves
            uint32_t ah[2][4], al[2][4], bh[5][2], bl[5][2];
            ldsm_x4(ah[0], aBase + aOffH + ksOff);
            ldsm_x4(ah[1], aBase + aOffH + 16 * GPITCH * 2 + ksOff);
            if (ALO) {
                ldsm_x4(al[0], aBase + aOffL + ksOff);
                ldsm_x4(al[1], aBase + aOffL + 16 * GPITCH * 2 + ksOff);
            }
            ldsm_x4(&bh[0][0], bBase + bOffH + ksOff);
            ldsm_x4(&bh[2][0], bBase + bOffH + 16 * GPITCH * 2 + ksOff);
            ldsm_x2(&bh[4][0], bBase + bOffH + 32 * GPITCH * 2 + ksOff);
            ldsm_x4(&bl[0][0], bBase + bOffL + ksOff);
            ldsm_x4(&bl[2][0], bBase + bOffL + 16 * GPITCH * 2 + ksOff);
            ldsm_x2(&bl[4][0], bBase + bOffL + 32 * GPITCH * 2 + ksOff);

            #pragma unroll
            for (int mi = 0; mi < 2; mi++)
                #pragma unroll
                for (int ni = 0; ni < 5; ni++) {
                    mma16816(acc[mi][ni], ah[mi], bh[ni]);
                    mma16816(acc[mi][ni], ah[mi], bl[ni]);
                    if (ALO) mma16816(acc[mi][ni], al[mi], bh[ni]);
                }
        }
        __syncthreads();
    }

    // ---- epilogue: bias + ELU + guarded store ----
    const int sel = nt / 5;
    const float* Bb = (sel == 0) ? Bb0 : (sel == 1 ? Bb1 : Bb2);
    const int cb = nt * 80 - sel * AD;
    #pragma unroll
    for (int mi = 0; mi < 2; mi++) {
        #pragma unroll
        for (int r01 = 0; r01 < 2; r01++) {
            const int row = bx * 128 + wm * 32 + mi * 16 + g4 + r01 * 8;
            if (row < M) {
                #pragma unroll
                for (int ni = 0; ni < 5; ni++) {
                    int lc = cb + wn * 40 + ni * 8 + l4 * 2;
                    float x0 = acc[mi][ni][r01 * 2 + 0] + Bb[lc];
                    float x1 = acc[mi][ni][r01 * 2 + 1] + Bb[lc + 1];
                    float o0 = (x0 > 0.f) ? x0 : expm1f(x0);
                    float o1 = (x1 > 0.f) ? x1 : expm1f(x1);
                    int col = nt * 80 + wn * 40 + ni * 8 + l4 * 2;
                    if (sizeof(OT) == 2) {
                        *reinterpret_cast<__half2*>((__half*)out + (long)row * NCAT + col)
                            = __floats2half2_rn(o0, o1);
                    } else {
                        *reinterpret_cast<float2*>((float*)out + (long)row * NCAT + col)
                            = make_float2(o0, o1);
                    }
                }
            }
        }
    }
}

// =====================================================================
// Word-level attention + target attention.  One block per (line, head).
// Reads fp16 q/k/v from g_vprojh (linear [tok][q|k|v] layout, R13-proven).
// =====================================================================
__global__ __launch_bounds__(128)
void watt_kernel(const int* __restrict__ docs, const float* __restrict__ w_tgt,
                 float* __restrict__ lineE)
{
    const int line = blockIdx.x;
    const int h    = blockIdx.y;
    const int tid  = threadIdx.x;

    __shared__ float q[WPL * DPH], k[WPL * DPH], v[WPL * DPH];
    __shared__ float ws[WPL * 33];
    __shared__ float watt[WPL * DPH];
    __shared__ float tw[WPL];
    __shared__ int   msk[WPL];
    __shared__ int   stok[WPL];

    if (tid < WPL) {
        int t = docs[line * WPL + tid];
        stok[tid] = t;
        msk[tid] = (t != 0);
    }
    __syncthreads();
    for (int i = tid; i < WPL * (DPH / 2); i += 128) {
        int w = i / (DPH / 2), d2 = i % (DPH / 2);
        long base = (long)stok[w] * NCAT + h * DPH + d2 * 2;
        float2 qf = __half22float2(*reinterpret_cast<const __half2*>(g_vprojh + base));
        float2 kf = __half22float2(*reinterpret_cast<const __half2*>(g_vprojh + base + AD));
        float2 vf = __half22float2(*reinterpret_cast<const __half2*>(g_vprojh + base + 2 * AD));
        int o = w * DPH + d2 * 2;
        q[o] = qf.x; q[o + 1] = qf.y;
        k[o] = kf.x; k[o + 1] = kf.y;
        v[o] = vf.x; v[o + 1] = vf.y;
    }
    __syncthreads();

    {
        int i0 = (tid >> 3) * 2;
        int j0 = (tid & 7) * 4;
        float s0[4] = {0.f, 0.f, 0.f, 0.f};
        float s1[4] = {0.f, 0.f, 0.f, 0.f};
        for (int d = 0; d < DPH; d++) {
            float qa = q[i0 * DPH + d];
            float qb = q[(i0 + 1) * DPH + d];
            #pragma unroll
            for (int jj = 0; jj < 4; jj++) {
                float kv = k[(j0 + jj) * DPH + d];
                s0[jj] = fmaf(qa, kv, s0[jj]);
                s1[jj] = fmaf(qb, kv, s1[jj]);
            }
        }
        #pragma unroll
        for (int jj = 0; jj < 4; jj++) {
            float m = msk[j0 + jj] ? 0.f : NEGPEN;
            ws[i0 * 33 + j0 + jj]       = s0[jj] * INV_SQRT50 - m;
            ws[(i0 + 1) * 33 + j0 + jj] = s1[jj] * INV_SQRT50 - m;
        }
    }
    __syncthreads();

    {
        int wi = tid >> 5, ln = tid & 31;
        for (int r = wi; r < WPL; r += 4) {
            float x = ws[r * 33 + ln];
            float mx = x;
            #pragma unroll
            for (int o = 16; o; o >>= 1) mx = fmaxf(mx, __shfl_xor_sync(~0u, mx, o));
            float e = __expf(x - mx);
            float sm = e;
            #pragma unroll
            for (int o = 16; o; o >>= 1) sm += __shfl_xor_sync(~0u, sm, o);
            float wv = e / sm;
            if (!msk[r]) wv = 0.f;
            ws[r * 33 + ln] = wv;
        }
    }
    __syncthreads();

    for (int u = tid; u < (WPL / 2) * DPH; u += 128) {
        int ip = u / DPH, d = u % DPH;
        int i0 = ip * 2;
        float a0 = 0.f, a1 = 0.f;
        for (int j = 0; j < WPL; j++) {
            float vv = v[j * DPH + d];
            a0 = fmaf(ws[i0 * 33 + j], vv, a0);
            a1 = fmaf(ws[(i0 + 1) * 33 + j], vv, a1);
        }
        watt[i0 * DPH + d] = a0;
        watt[(i0 + 1) * DPH + d] = a1;
    }
    __syncthreads();

    if (tid < WPL) {
        int j = tid;
        float s = 0.f;
        for (int d = 0; d < DPH; d++)
            s = fmaf(w_tgt[h * DPH + d], k[j * DPH + d], s);
        s *= INV_SQRT50;
        if (!msk[j]) s -= NEGPEN;
        float mx = s;
        #pragma unroll
        for (int o = 16; o; o >>= 1) mx = fmaxf(mx, __shfl_xor_sync(~0u, mx, o));
        float e = __expf(s - mx);
        float sm = e;
        #pragma unroll
        for (int o = 16; o; o >>= 1) sm += __shfl_xor_sync(~0u, sm, o);
        tw[j] = e / sm;
    }
    __syncthreads();

    if (tid < DPH) {
        int d = tid;
        float a = 0.f;
        for (int j = 0; j < WPL; j++) a = fmaf(tw[j], watt[j * DPH + d], a);
        lineE[(long)line * AD + h * DPH + d] = a;
    }
}

// =====================================================================
// Line-level attention + doc target attention.  One block per (doc, head).
// =====================================================================
#define LA_Q  0
#define LA_K  (LINES * DPH)
#define LA_V  (2 * LINES * DPH)
#define LA_A  (3 * LINES * DPH)
#define LA_S  (4 * LINES * DPH)
#define LA_FLOATS (LA_S + LINES * 129)
#define LA_SMEM_BYTES (LA_FLOATS * 4)
#define LA_THREADS 512

__global__ __launch_bounds__(LA_THREADS)
void latt_kernel(const int* __restrict__ docs, const float* __restrict__ l_tgt,
                 float* __restrict__ docE)
{
    extern __shared__ float sm[];
    __shared__ int   mskL[LINES];
    __shared__ float ts[LINES];

    const int doc = blockIdx.x;
    const int h   = blockIdx.y;
    const int tid = threadIdx.x;

    if (tid < LINES) {
        int any = 0;
        const int* p = docs + (long)(doc * LINES + tid) * WPL;
        for (int w = 0; w < WPL; w++) any |= p[w];
        mskL[tid] = (any != 0);
    }
    for (int i = tid; i < LINES * DPH; i += LA_THREADS) {
        int l = i / DPH, d = i % DPH;
        long base = (long)(doc * LINES + l) * NCAT + h * DPH + d;
        sm[LA_Q + i] = g_lqkv[base];
        sm[LA_K + i] = g_lqkv[base + AD];
        sm[LA_V + i] = g_lqkv[base + 2 * AD];
    }
    __syncthreads();

    for (int u = tid; u < (LINES / 2) * (LINES / 4); u += LA_THREADS) {
        int ip = u >> 5;
        int jq = u & 31;
        int i0 = ip * 2, j0 = jq * 4;
        float s0[4] = {0.f, 0.f, 0.f, 0.f};
        float s1[4] = {0.f, 0.f, 0.f, 0.f};
        for (int d = 0; d < DPH; d++) {
            float qa = sm[LA_Q + i0 * DPH + d];
            float qb = sm[LA_Q + (i0 + 1) * DPH + d];
            #pragma unroll
            for (int jj = 0; jj < 4; jj++) {
                float kv = sm[LA_K + (j0 + jj) * DPH + d];
                s0[jj] = fmaf(qa, kv, s0[jj]);
                s1[jj] = fmaf(qb, kv, s1[jj]);
            }
        }
        #pragma unroll
        for (int jj = 0; jj < 4; jj++) {
            float m = mskL[j0 + jj] ? 0.f : NEGPEN;
            sm[LA_S + i0 * 129 + j0 + jj]       = s0[jj] * INV_SQRT50 - m;
            sm[LA_S + (i0 + 1) * 129 + j0 + jj] = s1[jj] * INV_SQRT50 - m;
        }
    }
    __syncthreads();

    {
        int wi = tid >> 5, ln = tid & 31;
        for (int r = wi; r < LINES; r += (LA_THREADS / 32)) {
            float x0 = sm[LA_S + r * 129 + ln];
            float x1 = sm[LA_S + r * 129 + ln + 32];
            float x2 = sm[LA_S + r * 129 + ln + 64];
            float x3 = sm[LA_S + r * 129 + ln + 96];
            float mx = fmaxf(fmaxf(x0, x1), fmaxf(x2, x3));
            #pragma unroll
            for (int o = 16; o; o >>= 1) mx = fmaxf(mx, __shfl_xor_sync(~0u, mx, o));
            float e0 = __expf(x0 - mx), e1 = __expf(x1 - mx);
            float e2 = __expf(x2 - mx), e3 = __expf(x3 - mx);
            float smv = e0 + e1 + e2 + e3;
            #pragma unroll
            for (int o = 16; o; o >>= 1) smv += __shfl_xor_sync(~0u, smv, o);
            float inv = (mskL[r] ? 1.f : 0.f) / smv;
            sm[LA_S + r * 129 + ln]      = e0 * inv;
            sm[LA_S + r * 129 + ln + 32] = e1 * inv;
            sm[LA_S + r * 129 + ln + 64] = e2 * inv;
            sm[LA_S + r * 129 + ln + 96] = e3 * inv;
        }
    }
    __syncthreads();

    for (int u = tid; u < (LINES / 2) * DPH; u += LA_THREADS) {
        int ip = u / DPH, d = u % DPH;
        int i0 = ip * 2;
        float a0 = 0.f, a1 = 0.f;
        for (int j = 0; j < LINES; j++) {
            float vv = sm[LA_V + j * DPH + d];
            a0 = fmaf(sm[LA_S + i0 * 129 + j], vv, a0);
            a1 = fmaf(sm[LA_S + (i0 + 1) * 129 + j], vv, a1);
        }
        sm[LA_A + i0 * DPH + d] = a0;
        sm[LA_A + (i0 + 1) * DPH + d] = a1;
    }
    __syncthreads();

    if (tid < LINES) {
        int j = tid;
        float s = 0.f;
        for (int d = 0; d < DPH; d++)
            s = fmaf(l_tgt[h * DPH + d], sm[LA_K + j * DPH + d], s);
        s *= INV_SQRT50;
        if (!mskL[j]) s -= NEGPEN;
        ts[j] = s;
    }
    __syncthreads();
    if (tid < 32) {
        int ln = tid;
        float x0 = ts[ln], x1 = ts[ln + 32], x2 = ts[ln + 64], x3 = ts[ln + 96];
        float mx = fmaxf(fmaxf(x0, x1), fmaxf(x2, x3));
        #pragma unroll
        for (int o = 16; o; o >>= 1) mx = fmaxf(mx, __shfl_xor_sync(~0u, mx, o));
        float e0 = __expf(x0 - mx), e1 = __expf(x1 - mx);
        float e2 = __expf(x2 - mx), e3 = __expf(x3 - mx);
        float smv = e0 + e1 + e2 + e3;
        #pragma unroll
        for (int o = 16; o; o >>= 1) smv += __shfl_xor_sync(~0u, smv, o);
        float inv = 1.f / smv;
        ts[ln] = e0 * inv; ts[ln + 32] = e1 * inv;
        ts[ln + 64] = e2 * inv; ts[ln + 96] = e3 * inv;
    }
    __syncthreads();
    if (tid < DPH) {
        int d = tid;
        float a = 0.f;
        for (int j = 0; j < LINES; j++) a = fmaf(ts[j], sm[LA_A + j * DPH + d], a);
        docE[(long)doc * AD + h * DPH + d] = a;
    }
}

// =====================================================================
// Final FC
// =====================================================================
__global__ __launch_bounds__(608)
void fc_kernel(const float* __restrict__ fc1w, const float* __restrict__ fc1b,
               const float* __restrict__ fc2w, const float* __restrict__ fc2b,
               float* __restrict__ out)
{
    const int b = blockIdx.x;
    const int tid = threadIdx.x;
    __shared__ float de[AD];
    for (int i = tid; i < AD; i += 608) de[i] = g_docE[b * AD + i];
    __syncthreads();
    if (tid < 582) {
        float a;
        if (tid < 70) {
            a = fc1b[tid];
            for (int kk = 0; kk < AD; kk++) a = fmaf(de[kk], fc1w[kk * 70 + tid], a);
        } else {
            int c = tid - 70;
            a = fc2b[c];
            for (int kk = 0; kk < AD; kk++) a = fmaf(de[kk], fc2w[kk * 512 + c], a);
        }
        out[b * 582 + tid] = a;
    }
}

// =====================================================================
extern "C" void kernel_launch(void* const* d_in, const int* in_sizes, int n_in,
                              void* d_out, int out_size)
{
    const int*   docs  = (const int*)  d_in[0];
    const float* emb   = (const float*)d_in[1];
    const float* wq_w  = (const float*)d_in[2];
    const float* wq_b  = (const float*)d_in[3];
    const float* wk_w  = (const float*)d_in[4];
    const float* wk_b  = (const float*)d_in[5];
    const float* wv_w  = (const float*)d_in[6];
    const float* wv_b  = (const float*)d_in[7];
    const float* w_tgt = (const float*)d_in[8];
    const float* lq_w  = (const float*)d_in[9];
    const float* lq_b  = (const float*)d_in[10];
    const float* lk_w  = (const float*)d_in[11];
    const float* lk_b  = (const float*)d_in[12];
    const float* lv_w  = (const float*)d_in[13];
    const float* lv_b  = (const float*)d_in[14];
    const float* l_tgt = (const float*)d_in[15];
    const float* fc1_w = (const float*)d_in[16];
    const float* fc1_b = (const float*)d_in[17];
    const float* fc2_w = (const float*)d_in[18];
    const float* fc2_b = (const float*)d_in[19];
    float* out = (float*)d_out;

    float *lineE, *lqkv, *docE;
    __half *vprojh, *wbhi, *wblo, *ahi, *alo, *lbhi, *lblo, *a2hi, *a2lo;
    cudaGetSymbolAddress((void**)&vprojh, g_vprojh);
    cudaGetSymbolAddress((void**)&lineE, g_lineE);
    cudaGetSymbolAddress((void**)&lqkv,  g_lqkv);
    cudaGetSymbolAddress((void**)&docE,  g_docE);
    cudaGetSymbolAddress((void**)&wbhi,  g_WBhi);
    cudaGetSymbolAddress((void**)&wblo,  g_WBlo);
    cudaGetSymbolAddress((void**)&ahi,   g_Ahi);
    cudaGetSymbolAddress((void**)&alo,   g_Alo);
    cudaGetSymbolAddress((void**)&lbhi,  g_LBhi);
    cudaGetSymbolAddress((void**)&lblo,  g_LBlo);
    cudaGetSymbolAddress((void**)&a2hi,  g_A2hi);
    cudaGetSymbolAddress((void**)&a2lo,  g_A2lo);

    // 0) weight + emb splits
    splitW_kernel<<<(NCAT * (KPAD_W / 2) + 255) / 256, 256>>>(
        wq_w, wk_w, wv_w, EMB_D, KPAD_W, wbhi, wblo);
    splitW_kernel<<<(NCAT * (KPAD_L / 2) + 255) / 256, 256>>>(
        lq_w, lk_w, lv_w, AD, KPAD_L, lbhi, lblo);
    splitA_kernel<<<(int)(((long)VOCAB * (KPAD_W / 2) + 255) / 256), 256>>>(
        emb, VOCAB, EMB_D, KPAD_W, ahi, alo);

    // 1) vocab-wide word projection -> fp16 table (2-term: A_lo dropped)
    cudaFuncSetAttribute((const void*)gemm_elu_kernel<__half, false>,
                         cudaFuncAttributeMaxDynamicSharedMemorySize, GEMM_SMEM);
    cudaFuncSetAttribute((const void*)gemm_elu_kernel<float, true>,
                         cudaFuncAttributeMaxDynamicSharedMemorySize, GEMM_SMEM);
    gemm_elu_kernel<__half, false><<<dim3((VOCAB + 127) / 128, 15), 256, GEMM_SMEM>>>(
        ahi, alo, VOCAB, KPAD_W, KPAD_W / GKC,
        wbhi, wblo, wq_b, wk_b, wv_b, vprojh);

    // 2) word attention + target attention -> line_e [2048,400]
    watt_kernel<<<dim3(NLINE, HEADS), 128>>>(docs, w_tgt, lineE);

    // 3) line projection (fp32 output, full 3-term)
    splitA_kernel<<<(NLINE * (KPAD_L / 2) + 255) / 256, 256>>>(
        lineE, NLINE, AD, KPAD_L, a2hi, a2lo);
    gemm_elu_kernel<float, true><<<dim3(NLINE / 128, 15), 256, GEMM_SMEM>>>(
        a2hi, a2lo, NLINE, KPAD_L, KPAD_L / GKC,
        lbhi, lblo, lq_b, lk_b, lv_b, lqkv);

    // 4) line attention + doc target attention -> doc_e [16,400]
    cudaFuncSetAttribute(latt_kernel, cudaFuncAttributeMaxDynamicSharedMemorySize,
                         LA_SMEM_BYTES);
    latt_kernel<<<dim3(B_SZ, HEADS), LA_THREADS, LA_SMEM_BYTES>>>(docs, l_tgt, docE);

    // 5) final FC -> [16,582]
    fc_kernel<<<B_SZ, 608>>>(fc1_w, fc1_b, fc2_w, fc2_b, out);
}